// round 1
// baseline (speedup 1.0000x reference)
#include <cuda_runtime.h>
#include <math.h>

// Problem constants (fixed by the dataset)
#define N_SEQ   1024
#define L_SEQ   64
#define NINP    512
#define NREL    200
#define EPS_E   32            // edges per sequence (m is constant 32)
#define SEQ_PB  8             // sequences per block in kernel B
#define GRID_B  (N_SEQ / SEQ_PB)  // 128 blocks

// Scratch + accumulators (no allocations allowed)
__device__ float               g_h[N_SEQ * NINP];   // 2 MB intermediate h = emb[seq].sum(1)
__device__ double              g_logp    = 0.0;
__device__ unsigned long long  g_correct = 0ull;
__device__ unsigned int        g_done    = 0u;

// ---------------------------------------------------------------------------
// Kernel 1: h[i,:] = sum_j emb[seq[i,j], :]
// 1024 blocks x 256 threads; each thread owns 2 consecutive columns (float2).
// Token ids staged in smem; unroll for memory-level parallelism.
// ---------------------------------------------------------------------------
__global__ void __launch_bounds__(256) gather_kernel(const int* __restrict__ seq,
                                                     const float* __restrict__ emb) {
    __shared__ int toks[L_SEQ];
    const int i = blockIdx.x;
    const int t = threadIdx.x;
    if (t < L_SEQ) toks[t] = seq[i * L_SEQ + t];
    __syncthreads();

    const int c = t * 2;
    float ax = 0.f, ay = 0.f;
#pragma unroll 8
    for (int j = 0; j < L_SEQ; j++) {
        const float2 v = *reinterpret_cast<const float2*>(
            emb + (size_t)toks[j] * NINP + c);
        ax += v.x;
        ay += v.y;
    }
    float2 o; o.x = ax; o.y = ay;
    *reinterpret_cast<float2*>(g_h + (size_t)i * NINP + c) = o;
}

// ---------------------------------------------------------------------------
// Kernel 2: logit = h @ W^T + b ; fused mask build + loss + accuracy reduce.
// 128 blocks x 256 threads. Block handles 8 sequences, thread r (< 200)
// handles one relation: 8 dot products of length 512 (float4, smem-broadcast h).
// ---------------------------------------------------------------------------
__global__ void __launch_bounds__(256) logit_loss_kernel(const int* __restrict__ rel,
                                                         const float* __restrict__ W,
                                                         const float* __restrict__ b,
                                                         float* __restrict__ out) {
    __shared__ float         h_s[SEQ_PB][NINP];        // 16 KB
    __shared__ unsigned char mask_s[SEQ_PB][256];      // 2 KB (NREL padded to 256)
    __shared__ float         red_f[256];
    __shared__ int           red_i[256];

    const int tid = threadIdx.x;
    const int blk = blockIdx.x;

    // Cooperative load of the 8 h vectors (coalesced float4)
    {
        const float4* src = reinterpret_cast<const float4*>(
            g_h + (size_t)blk * SEQ_PB * NINP);
        float4* dst = reinterpret_cast<float4*>(&h_s[0][0]);
#pragma unroll
        for (int i = 0; i < (SEQ_PB * NINP / 4) / 256; i++)   // 4 iters
            dst[tid + i * 256] = src[tid + i * 256];
    }
    // Zero mask (8*256 bytes = 512 ints)
    {
        int* mz = reinterpret_cast<int*>(&mask_s[0][0]);
        mz[tid]       = 0;
        mz[tid + 256] = 0;
    }
    __syncthreads();

    // Set mask: 8 seqs * 32 edges = 256 edges -> one per thread.
    // edge e = blk*256 + tid belongs to local sequence (tid >> 5).
    {
        const int r = rel[blk * 256 + tid];
        mask_s[tid >> 5][r] = 1;
    }
    __syncthreads();

    float lp   = 0.f;
    int   corr = 0;

    if (tid < NREL) {
        const int r = tid;
        float acc[SEQ_PB];
#pragma unroll
        for (int s = 0; s < SEQ_PB; s++) acc[s] = 0.f;

        const float4* wr = reinterpret_cast<const float4*>(W + (size_t)r * NINP);
#pragma unroll 4
        for (int k4 = 0; k4 < NINP / 4; k4++) {
            const float4 w = __ldg(wr + k4);
#pragma unroll
            for (int s = 0; s < SEQ_PB; s++) {
                const float4 hv = *reinterpret_cast<const float4*>(&h_s[s][k4 * 4]);
                acc[s] += w.x * hv.x;
                acc[s] += w.y * hv.y;
                acc[s] += w.z * hv.z;
                acc[s] += w.w * hv.w;
            }
        }

        const float bb = b[r];
#pragma unroll
        for (int s = 0; s < SEQ_PB; s++) {
            const float x   = acc[s] + bb;
            const bool  msk = (mask_s[s][r] != 0);
            float val;
            if (msk) {
                // log_sigmoid(x), numerically stable
                val = fminf(x, 0.f) - log1pf(expf(-fabsf(x)));
            } else {
                // log(1 + 1e-5 - sigmoid(x)) = log(sigmoid(-x) + 1e-5)
                val = logf(1.0f / (1.0f + expf(x)) + 1e-5f);
            }
            lp   += val;
            corr += ((x > 0.5f) == msk) ? 1 : 0;
        }
    }

    // Block reduction
    red_f[tid] = lp;
    red_i[tid] = corr;
    __syncthreads();
#pragma unroll
    for (int st = 128; st > 0; st >>= 1) {
        if (tid < st) {
            red_f[tid] += red_f[tid + st];
            red_i[tid] += red_i[tid + st];
        }
        __syncthreads();
    }

    if (tid == 0) {
        atomicAdd(&g_logp, (double)red_f[0]);
        atomicAdd(&g_correct, (unsigned long long)red_i[0]);
        __threadfence();
        const unsigned int done = atomicAdd(&g_done, 1u);
        if (done == (unsigned int)(gridDim.x - 1)) {
            // Final normalization: sum / N ; mean over N*NREL predictions
            const double logp  = g_logp / (double)N_SEQ;
            const double acc_v = (double)g_correct / ((double)N_SEQ * (double)NREL);
            out[0] = (float)logp;
            out[1] = (float)acc_v;
            // Reset for next graph replay (deterministic, same work each call)
            g_logp    = 0.0;
            g_correct = 0ull;
            g_done    = 0u;
        }
    }
}

// ---------------------------------------------------------------------------
extern "C" void kernel_launch(void* const* d_in, const int* in_sizes, int n_in,
                              void* d_out, int out_size) {
    const int*   seq = (const int*)d_in[0];
    // d_in[1] = m (constant 32 per sequence; layout hardcoded)
    const int*   rel = (const int*)d_in[2];
    const float* emb = (const float*)d_in[3];
    const float* W   = (const float*)d_in[4];
    const float* b   = (const float*)d_in[5];
    float*       out = (float*)d_out;

    gather_kernel<<<N_SEQ, 256>>>(seq, emb);
    logit_loss_kernel<<<GRID_B, 256>>>(rel, W, b, out);
}

// round 6
// speedup vs baseline: 1.1728x; 1.1728x over previous
#include <cuda_runtime.h>
#include <math.h>

// Problem constants (fixed by the dataset)
#define N_SEQ   1024
#define L_SEQ   64
#define NINP    512
#define NREL    200
#define EPS_E   32

// GEMM tiling: 200 = 5 * 40 (no padding waste)
#define SEQT    64            // seqs per block tile
#define RELT    40            // rels per block tile
#define KSPLIT  4             // K split factor (chunks of 128)
#define KCHUNK  (NINP / KSPLIT)   // 128
#define KC      16            // smem stage depth
#define TGX     16            // thread grid x (seq groups)
#define TGY     10            // thread grid y (rel groups)
#define NTHR    (TGX * TGY)   // 160 threads

// Loss kernel
#define SEQ_PB  4
#define GRID_L  (N_SEQ / SEQ_PB)  // 256 blocks

// Scratch (no allocations allowed)
__device__ float               g_h[N_SEQ * NINP];                    // 2 MB
__device__ float               g_part[KSPLIT * N_SEQ * NREL];       // 3.28 MB
__device__ double              g_logp    = 0.0;
__device__ unsigned long long  g_correct = 0ull;
__device__ unsigned int        g_done    = 0u;

// ---------------------------------------------------------------------------
// Kernel 1: h[i,:] = sum_j emb[seq[i,j], :]   (L2-resident gather, ~cap-bound)
// ---------------------------------------------------------------------------
__global__ void __launch_bounds__(256) gather_kernel(const int* __restrict__ seq,
                                                     const float* __restrict__ emb) {
    __shared__ int toks[L_SEQ];
    const int i = blockIdx.x;
    const int t = threadIdx.x;
    if (t < L_SEQ) toks[t] = seq[i * L_SEQ + t];
    __syncthreads();

    const int c = t * 2;
    float ax = 0.f, ay = 0.f;
#pragma unroll 8
    for (int j = 0; j < L_SEQ; j++) {
        const float2 v = *reinterpret_cast<const float2*>(
            emb + (size_t)toks[j] * NINP + c);
        ax += v.x;
        ay += v.y;
    }
    float2 o; o.x = ax; o.y = ay;
    *reinterpret_cast<float2*>(g_h + (size_t)i * NINP + c) = o;
}

// ---------------------------------------------------------------------------
// Kernel 2: register-tiled SGEMM with split-K.
// Block (bx, by, bz): seqs [bx*64, +64), rels [by*40, +40), K [bz*128, +128).
// 160 threads; thread (sx, ry) computes 4 seqs x 4 rels.
// Partials written to g_part[bz][seq][rel].
// ---------------------------------------------------------------------------
__global__ void __launch_bounds__(NTHR) sgemm_kernel(const float* __restrict__ W) {
    __shared__ float h_s[KC][SEQT];   // k-major h tile (4 KB)
    __shared__ float w_s[KC][RELT];   // k-major W tile (2.5 KB)

    const int tid = threadIdx.x;
    const int sx  = tid % TGX;        // seq group 0..15
    const int ry  = tid / TGX;        // rel group 0..9

    const int seqBase = blockIdx.x * SEQT;
    const int relBase = blockIdx.y * RELT;
    const int kb0     = blockIdx.z * KCHUNK;

    float acc[4][4];
#pragma unroll
    for (int a = 0; a < 4; a++)
#pragma unroll
        for (int c = 0; c < 4; c++) acc[a][c] = 0.f;

    for (int st = 0; st < KCHUNK / KC; st++) {       // 8 stages
        const int kb = kb0 + st * KC;

        // Fill h_s: 64 seqs x 16 k = 256 float4 loads, transposed store
        for (int i = tid; i < (SEQT * KC) / 4; i += NTHR) {
            const int s  = i >> 2;          // 0..63
            const int k4 = i & 3;           // 0..3
            const float4 v = *reinterpret_cast<const float4*>(
                g_h + (size_t)(seqBase + s) * NINP + kb + k4 * 4);
            h_s[k4 * 4 + 0][s] = v.x;
            h_s[k4 * 4 + 1][s] = v.y;
            h_s[k4 * 4 + 2][s] = v.z;
            h_s[k4 * 4 + 3][s] = v.w;
        }
        // Fill w_s: 40 rels x 16 k = 160 float4 loads (exactly 1/thread)
        {
            const int r  = tid >> 2;        // 0..39
            const int k4 = tid & 3;         // 0..3
            const float4 v = *reinterpret_cast<const float4*>(
                W + (size_t)(relBase + r) * NINP + kb + k4 * 4);
            w_s[k4 * 4 + 0][r] = v.x;
            w_s[k4 * 4 + 1][r] = v.y;
            w_s[k4 * 4 + 2][r] = v.z;
            w_s[k4 * 4 + 3][r] = v.w;
        }
        __syncthreads();

#pragma unroll
        for (int k = 0; k < KC; k++) {
            const float4 a = *reinterpret_cast<const float4*>(&h_s[k][sx * 4]);
            const float4 w = *reinterpret_cast<const float4*>(&w_s[k][ry * 4]);
            const float av[4] = {a.x, a.y, a.z, a.w};
            const float wv[4] = {w.x, w.y, w.z, w.w};
#pragma unroll
            for (int i = 0; i < 4; i++)
#pragma unroll
                for (int j = 0; j < 4; j++)
                    acc[i][j] += av[i] * wv[j];
        }
        __syncthreads();
    }

    // Store partials (float4 per seq row)
    float* base = g_part + ((size_t)blockIdx.z * N_SEQ + seqBase + sx * 4) * NREL
                  + relBase + ry * 4;
#pragma unroll
    for (int i = 0; i < 4; i++) {
        float4 o;
        o.x = acc[i][0]; o.y = acc[i][1]; o.z = acc[i][2]; o.w = acc[i][3];
        *reinterpret_cast<float4*>(base + (size_t)i * NREL) = o;
    }
}

// ---------------------------------------------------------------------------
// Kernel 3: sum split-K partials + bias, build mask, fused loss + acc reduce.
// 256 blocks x 256 threads; 4 seqs per block; thread r < 200 handles 1 rel.
// ---------------------------------------------------------------------------
__global__ void __launch_bounds__(256) loss_kernel(const int* __restrict__ rel,
                                                   const float* __restrict__ b,
                                                   float* __restrict__ out) {
    __shared__ unsigned char mask_s[SEQ_PB][256];
    __shared__ float         red_f[256];
    __shared__ int           red_i[256];

    const int tid = threadIdx.x;
    const int blk = blockIdx.x;
    const int seq0 = blk * SEQ_PB;

    // Zero mask (4*256 bytes = 256 ints)
    reinterpret_cast<int*>(&mask_s[0][0])[tid] = 0;
    __syncthreads();

    // Set mask: 4 seqs * 32 edges = 128 edges
    if (tid < SEQ_PB * EPS_E) {
        const int r = rel[blk * (SEQ_PB * EPS_E) + tid];
        mask_s[tid >> 5][r] = 1;
    }
    __syncthreads();

    float lp   = 0.f;
    int   corr = 0;

    if (tid < NREL) {
        const float bb = b[tid];
#pragma unroll
        for (int s = 0; s < SEQ_PB; s++) {
            const size_t idx = (size_t)(seq0 + s) * NREL + tid;
            float x = bb;
#pragma unroll
            for (int ks = 0; ks < KSPLIT; ks++)
                x += g_part[(size_t)ks * N_SEQ * NREL + idx];

            const bool msk = (mask_s[s][tid] != 0);
            float val;
            if (msk) {
                val = fminf(x, 0.f) - log1pf(expf(-fabsf(x)));
            } else {
                val = logf(1.0f / (1.0f + expf(x)) + 1e-5f);
            }
            lp   += val;
            corr += ((x > 0.5f) == msk) ? 1 : 0;
        }
    }

    red_f[tid] = lp;
    red_i[tid] = corr;
    __syncthreads();
#pragma unroll
    for (int st = 128; st > 0; st >>= 1) {
        if (tid < st) {
            red_f[tid] += red_f[tid + st];
            red_i[tid] += red_i[tid + st];
        }
        __syncthreads();
    }

    if (tid == 0) {
        atomicAdd(&g_logp, (double)red_f[0]);
        atomicAdd(&g_correct, (unsigned long long)red_i[0]);
        __threadfence();
        const unsigned int done = atomicAdd(&g_done, 1u);
        if (done == (unsigned int)(gridDim.x - 1)) {
            const double logp  = g_logp / (double)N_SEQ;
            const double acc_v = (double)g_correct / ((double)N_SEQ * (double)NREL);
            out[0] = (float)logp;
            out[1] = (float)acc_v;
            g_logp    = 0.0;
            g_correct = 0ull;
            g_done    = 0u;
        }
    }
}

// ---------------------------------------------------------------------------
extern "C" void kernel_launch(void* const* d_in, const int* in_sizes, int n_in,
                              void* d_out, int out_size) {
    const int*   seq = (const int*)d_in[0];
    const int*   rel = (const int*)d_in[2];
    const float* emb = (const float*)d_in[3];
    const float* W   = (const float*)d_in[4];
    const float* b   = (const float*)d_in[5];
    float*       out = (float*)d_out;

    gather_kernel<<<N_SEQ, 256>>>(seq, emb);
    dim3 gg(N_SEQ / SEQT, NREL / RELT, KSPLIT);   // 16 x 5 x 4 = 320 blocks
    sgemm_kernel<<<gg, NTHR>>>(W);
    loss_kernel<<<GRID_L, 256>>>(rel, b, out);
}